// round 1
// baseline (speedup 1.0000x reference)
#include <cuda_runtime.h>
#include <cuda_bf16.h>
#include <math_constants.h>

// ---------------------------------------------------------------------------
// Problem constants
//   x:      [4, 256, 64, 64] f32
//   w_qkv:  [768, 256], b_qkv: [768]
//   w_pe:   [256, 1, 7, 7], b_pe: [256]
//   w_proj: [256, 256], b_proj: [256]
//   out:    [4, 256, 64, 64] f32
// Area attention: 16 strips (b*4 + y/16) x 8 heads, each 1024x1024x32.
// ---------------------------------------------------------------------------

#define NGLOB 16384      // 4 * 4096 pixels
#define CIN   256
#define C3    768

// Intermediates (channel-major [chan][NGLOB])
__device__ float g_qkv[C3 * NGLOB];        // rows: h*96 + {0:q,32:k,64:v} + d
__device__ float g_att[CIN * NGLOB];       // attention output, c = h*32+d
__device__ float g_t  [CIN * NGLOB];       // attn + dwconv(v) + b_pe

// ---------------------------------------------------------------------------
// Kernel 1: qkv GEMM.  g_qkv[o][ng] = b_qkv[o] + sum_c w[o][c] * x[b][c][n]
// 128x128 tile, BK=16, 256 threads, 8x8 microtile.
// ---------------------------------------------------------------------------
__global__ void __launch_bounds__(256) gemm_qkv_kernel(
    const float* __restrict__ x, const float* __restrict__ w,
    const float* __restrict__ bias)
{
    __shared__ float As[16][132];
    __shared__ float Bs[16][132];

    const int tid = threadIdx.x;
    const int m0  = blockIdx.y * 128;
    const int ng0 = blockIdx.x * 128;
    const int b   = ng0 >> 12;
    const int n0  = ng0 & 4095;
    const float* xb = x + (size_t)b * (CIN * 4096) + n0;

    float acc[8][8];
#pragma unroll
    for (int i = 0; i < 8; i++)
#pragma unroll
        for (int j = 0; j < 8; j++) acc[i][j] = 0.f;

    const int ty = tid >> 4, tx = tid & 15;
    const int ar = tid >> 1;             // 0..127  A row
    const int ak = (tid & 1) * 8;        // 0 or 8  A k-offset
    const int bk = tid >> 4;             // 0..15   B k row
    const int bc = (tid & 15) * 8;       // B col offset

    for (int kb = 0; kb < CIN; kb += 16) {
        __syncthreads();
        {
            const float* ap = w + (size_t)(m0 + ar) * CIN + kb + ak;
            float4 a0 = *(const float4*)ap;
            float4 a1 = *(const float4*)(ap + 4);
            As[ak + 0][ar] = a0.x; As[ak + 1][ar] = a0.y;
            As[ak + 2][ar] = a0.z; As[ak + 3][ar] = a0.w;
            As[ak + 4][ar] = a1.x; As[ak + 5][ar] = a1.y;
            As[ak + 6][ar] = a1.z; As[ak + 7][ar] = a1.w;
            const float* bp = xb + (size_t)(kb + bk) * 4096 + bc;
            *(float4*)&Bs[bk][bc]     = *(const float4*)bp;
            *(float4*)&Bs[bk][bc + 4] = *(const float4*)(bp + 4);
        }
        __syncthreads();
#pragma unroll
        for (int k = 0; k < 16; k++) {
            float4 a0 = *(float4*)&As[k][ty * 8];
            float4 a1 = *(float4*)&As[k][ty * 8 + 4];
            float4 b0 = *(float4*)&Bs[k][tx * 8];
            float4 b1 = *(float4*)&Bs[k][tx * 8 + 4];
            float av[8] = {a0.x, a0.y, a0.z, a0.w, a1.x, a1.y, a1.z, a1.w};
            float bv[8] = {b0.x, b0.y, b0.z, b0.w, b1.x, b1.y, b1.z, b1.w};
#pragma unroll
            for (int i = 0; i < 8; i++)
#pragma unroll
                for (int j = 0; j < 8; j++) acc[i][j] += av[i] * bv[j];
        }
    }

#pragma unroll
    for (int i = 0; i < 8; i++) {
        const int o = m0 + ty * 8 + i;
        const float bo = bias[o];
        float* dst = g_qkv + (size_t)o * NGLOB + ng0 + tx * 8;
        float4 r0 = make_float4(acc[i][0] + bo, acc[i][1] + bo,
                                acc[i][2] + bo, acc[i][3] + bo);
        float4 r1 = make_float4(acc[i][4] + bo, acc[i][5] + bo,
                                acc[i][6] + bo, acc[i][7] + bo);
        *(float4*)dst = r0;
        *(float4*)(dst + 4) = r1;
    }
}

// ---------------------------------------------------------------------------
// Kernel 2: flash attention.
// grid = (8 qtiles, 8 heads, 16 strips), 256 threads.
// Q tile 128x32, K/V tiles 64x32, fp32.
// smem: q_s[32][132] (d-major), k_s/v_s[32][68], p_s[64][132] (j-major).
// ---------------------------------------------------------------------------
#define QS_OFF 0
#define KS_OFF (32 * 132)
#define VS_OFF (KS_OFF + 32 * 68)
#define PS_OFF (VS_OFF + 32 * 68)
#define ATT_SMEM_BYTES ((PS_OFF + 64 * 132) * 4)

__global__ void __launch_bounds__(256, 2) attn_kernel()
{
    extern __shared__ float smf[];
    float* q_s = smf + QS_OFF;
    float* k_s = smf + KS_OFF;
    float* v_s = smf + VS_OFF;
    float* p_s = smf + PS_OFF;

    const int tid = threadIdx.x;
    const int qt = blockIdx.x, h = blockIdx.y, ba = blockIdx.z;
    const int b = ba >> 2, strip = ba & 3;
    const int colbase = b * 4096 + strip * 1024;
    const int qcol = colbase + qt * 128;
    const float scale = 0.17677669529663687f;  // 1/sqrt(32)

    // Load+scale Q tile: q_s[d][i]
    {
        const int d = tid >> 3;
        const int i0 = (tid & 7) * 16;
        const float* src = g_qkv + (size_t)(h * 96 + d) * NGLOB + qcol + i0;
        float* dst = q_s + d * 132 + i0;
#pragma unroll
        for (int q = 0; q < 16; q += 4) {
            float4 v = *(const float4*)(src + q);
            v.x *= scale; v.y *= scale; v.z *= scale; v.w *= scale;
            *(float4*)(dst + q) = v;
        }
    }

    const int ti = tid >> 4, tj = tid & 15;
    const int i0 = ti * 8;

    float m_i[8], l_i[8], acc[8][2];
#pragma unroll
    for (int i = 0; i < 8; i++) {
        m_i[i] = -CUDART_INF_F; l_i[i] = 0.f; acc[i][0] = 0.f; acc[i][1] = 0.f;
    }

    const int ld = tid >> 3;             // loader d row
    const int lj = (tid & 7) * 8;        // loader j offset

    for (int jt = 0; jt < 16; jt++) {
        __syncthreads();   // prev readers of k_s/v_s/p_s done
        {
            const float* ks = g_qkv + (size_t)(h * 96 + 32 + ld) * NGLOB + colbase + jt * 64 + lj;
            const float* vs = g_qkv + (size_t)(h * 96 + 64 + ld) * NGLOB + colbase + jt * 64 + lj;
            *(float4*)(k_s + ld * 68 + lj)     = *(const float4*)ks;
            *(float4*)(k_s + ld * 68 + lj + 4) = *(const float4*)(ks + 4);
            *(float4*)(v_s + ld * 68 + lj)     = *(const float4*)vs;
            *(float4*)(v_s + ld * 68 + lj + 4) = *(const float4*)(vs + 4);
        }
        __syncthreads();

        // S tile: 8 i-rows x 4 j-cols per thread
        float s[8][4];
#pragma unroll
        for (int i = 0; i < 8; i++)
#pragma unroll
            for (int j = 0; j < 4; j++) s[i][j] = 0.f;

#pragma unroll 8
        for (int d = 0; d < 32; d++) {
            float4 qa = *(float4*)(q_s + d * 132 + i0);
            float4 qb = *(float4*)(q_s + d * 132 + i0 + 4);
            float4 kf = *(float4*)(k_s + d * 68 + tj * 4);
            float qv[8] = {qa.x, qa.y, qa.z, qa.w, qb.x, qb.y, qb.z, qb.w};
            float kv[4] = {kf.x, kf.y, kf.z, kf.w};
#pragma unroll
            for (int i = 0; i < 8; i++)
#pragma unroll
                for (int j = 0; j < 4; j++) s[i][j] += qv[i] * kv[j];
        }

        // Online softmax (row stats across 16-lane tj groups)
#pragma unroll
        for (int i = 0; i < 8; i++) {
            float mx = fmaxf(fmaxf(s[i][0], s[i][1]), fmaxf(s[i][2], s[i][3]));
            mx = fmaxf(mx, __shfl_xor_sync(0xffffffffu, mx, 1));
            mx = fmaxf(mx, __shfl_xor_sync(0xffffffffu, mx, 2));
            mx = fmaxf(mx, __shfl_xor_sync(0xffffffffu, mx, 4));
            mx = fmaxf(mx, __shfl_xor_sync(0xffffffffu, mx, 8));
            float mnew = fmaxf(m_i[i], mx);
            float cf = __expf(m_i[i] - mnew);
            m_i[i] = mnew;
            float rs = 0.f;
#pragma unroll
            for (int j = 0; j < 4; j++) {
                float p = __expf(s[i][j] - mnew);
                s[i][j] = p;
                rs += p;
            }
            rs += __shfl_xor_sync(0xffffffffu, rs, 1);
            rs += __shfl_xor_sync(0xffffffffu, rs, 2);
            rs += __shfl_xor_sync(0xffffffffu, rs, 4);
            rs += __shfl_xor_sync(0xffffffffu, rs, 8);
            l_i[i] = l_i[i] * cf + rs;
            acc[i][0] *= cf;
            acc[i][1] *= cf;
        }

        // stage P to smem: p_s[j][i]
#pragma unroll
        for (int j = 0; j < 4; j++) {
            *(float4*)(p_s + (tj * 4 + j) * 132 + i0) =
                make_float4(s[0][j], s[1][j], s[2][j], s[3][j]);
            *(float4*)(p_s + (tj * 4 + j) * 132 + i0 + 4) =
                make_float4(s[4][j], s[5][j], s[6][j], s[7][j]);
        }
        __syncthreads();

        // O += P @ V : thread owns 8 i-rows x 2 d-cols (d0 = 2*tj)
        const int d0 = 2 * tj;
#pragma unroll 4
        for (int j4 = 0; j4 < 64; j4 += 4) {
            float4 va = *(float4*)(v_s + d0 * 68 + j4);
            float4 vb = *(float4*)(v_s + (d0 + 1) * 68 + j4);
            float vA[4] = {va.x, va.y, va.z, va.w};
            float vB[4] = {vb.x, vb.y, vb.z, vb.w};
#pragma unroll
            for (int jj = 0; jj < 4; jj++) {
                float4 pa = *(float4*)(p_s + (j4 + jj) * 132 + i0);
                float4 pb = *(float4*)(p_s + (j4 + jj) * 132 + i0 + 4);
                float pv[8] = {pa.x, pa.y, pa.z, pa.w, pb.x, pb.y, pb.z, pb.w};
#pragma unroll
                for (int i = 0; i < 8; i++) {
                    acc[i][0] += pv[i] * vA[jj];
                    acc[i][1] += pv[i] * vB[jj];
                }
            }
        }
    }

    // normalize + store: g_att[(h*32+d)][col]
    float inv[8];
#pragma unroll
    for (int i = 0; i < 8; i++) inv[i] = 1.f / l_i[i];
    const int d0 = 2 * tj;
#pragma unroll
    for (int dd = 0; dd < 2; dd++) {
        float* dst = g_att + (size_t)(h * 32 + d0 + dd) * NGLOB + qcol + i0;
        float4 o0 = make_float4(acc[0][dd] * inv[0], acc[1][dd] * inv[1],
                                acc[2][dd] * inv[2], acc[3][dd] * inv[3]);
        float4 o1 = make_float4(acc[4][dd] * inv[4], acc[5][dd] * inv[5],
                                acc[6][dd] * inv[6], acc[7][dd] * inv[7]);
        *(float4*)dst = o0;
        *(float4*)(dst + 4) = o1;
    }
}

// ---------------------------------------------------------------------------
// Kernel 3: 7x7 depthwise conv on V + add attention output + b_pe -> g_t
// grid = (256 channels, 4 batches), 256 threads, one 64x64 plane per CTA.
// ---------------------------------------------------------------------------
__global__ void __launch_bounds__(256) dwconv_kernel(
    const float* __restrict__ wpe, const float* __restrict__ bpe)
{
    __shared__ float sm[70][72];
    __shared__ float wk[49];

    const int c = blockIdx.x, b = blockIdx.y;
    const int tid = threadIdx.x;

    for (int i = tid; i < 70 * 72; i += 256) (&sm[0][0])[i] = 0.f;
    if (tid < 49) wk[tid] = wpe[c * 49 + tid];
    __syncthreads();

    const int vrow = (c >> 5) * 96 + 64 + (c & 31);
    const float* vsrc = g_qkv + (size_t)vrow * NGLOB + b * 4096;
    const int r  = tid >> 2;           // 0..63 row
    const int c0 = (tid & 3) * 16;     // col offset
#pragma unroll
    for (int q = 0; q < 16; q += 4) {
        float4 v = *(const float4*)(vsrc + r * 64 + c0 + q);
        sm[3 + r][3 + c0 + q + 0] = v.x;
        sm[3 + r][3 + c0 + q + 1] = v.y;
        sm[3 + r][3 + c0 + q + 2] = v.z;
        sm[3 + r][3 + c0 + q + 3] = v.w;
    }
    __syncthreads();

    const float* asrc = g_att + (size_t)c * NGLOB + b * 4096;
    const float bb = bpe[c];
    float out[16];
#pragma unroll
    for (int q = 0; q < 16; q += 4) {
        float4 a = *(const float4*)(asrc + r * 64 + c0 + q);
        out[q + 0] = a.x + bb; out[q + 1] = a.y + bb;
        out[q + 2] = a.z + bb; out[q + 3] = a.w + bb;
    }

#pragma unroll
    for (int ky = 0; ky < 7; ky++) {
        float row[22];
#pragma unroll
        for (int q = 0; q < 22; q++) row[q] = sm[r + ky][c0 + q];
#pragma unroll
        for (int kx = 0; kx < 7; kx++) {
            const float wv = wk[ky * 7 + kx];
#pragma unroll
            for (int xx = 0; xx < 16; xx++) out[xx] += wv * row[xx + kx];
        }
    }

    float* dst = g_t + (size_t)c * NGLOB + b * 4096 + r * 64 + c0;
#pragma unroll
    for (int q = 0; q < 16; q += 4)
        *(float4*)(dst + q) = make_float4(out[q], out[q + 1], out[q + 2], out[q + 3]);
}

// ---------------------------------------------------------------------------
// Kernel 4: projection GEMM -> d_out (NCHW) + bias
// ---------------------------------------------------------------------------
__global__ void __launch_bounds__(256) gemm_proj_kernel(
    const float* __restrict__ w, const float* __restrict__ bias,
    float* __restrict__ outp)
{
    __shared__ float As[16][132];
    __shared__ float Bs[16][132];

    const int tid = threadIdx.x;
    const int m0  = blockIdx.y * 128;
    const int ng0 = blockIdx.x * 128;
    const int b   = ng0 >> 12;
    const int n0  = ng0 & 4095;

    float acc[8][8];
#pragma unroll
    for (int i = 0; i < 8; i++)
#pragma unroll
        for (int j = 0; j < 8; j++) acc[i][j] = 0.f;

    const int ty = tid >> 4, tx = tid & 15;
    const int ar = tid >> 1;
    const int ak = (tid & 1) * 8;
    const int bk = tid >> 4;
    const int bc = (tid & 15) * 8;

    for (int kb = 0; kb < CIN; kb += 16) {
        __syncthreads();
        {
            const float* ap = w + (size_t)(m0 + ar) * CIN + kb + ak;
            float4 a0 = *(const float4*)ap;
            float4 a1 = *(const float4*)(ap + 4);
            As[ak + 0][ar] = a0.x; As[ak + 1][ar] = a0.y;
            As[ak + 2][ar] = a0.z; As[ak + 3][ar] = a0.w;
            As[ak + 4][ar] = a1.x; As[ak + 5][ar] = a1.y;
            As[ak + 6][ar] = a1.z; As[ak + 7][ar] = a1.w;
            const float* bp = g_t + (size_t)(kb + bk) * NGLOB + ng0 + bc;
            *(float4*)&Bs[bk][bc]     = *(const float4*)bp;
            *(float4*)&Bs[bk][bc + 4] = *(const float4*)(bp + 4);
        }
        __syncthreads();
#pragma unroll
        for (int k = 0; k < 16; k++) {
            float4 a0 = *(float4*)&As[k][ty * 8];
            float4 a1 = *(float4*)&As[k][ty * 8 + 4];
            float4 b0 = *(float4*)&Bs[k][tx * 8];
            float4 b1 = *(float4*)&Bs[k][tx * 8 + 4];
            float av[8] = {a0.x, a0.y, a0.z, a0.w, a1.x, a1.y, a1.z, a1.w};
            float bv[8] = {b0.x, b0.y, b0.z, b0.w, b1.x, b1.y, b1.z, b1.w};
#pragma unroll
            for (int i = 0; i < 8; i++)
#pragma unroll
                for (int j = 0; j < 8; j++) acc[i][j] += av[i] * bv[j];
        }
    }

#pragma unroll
    for (int i = 0; i < 8; i++) {
        const int o = m0 + ty * 8 + i;
        const float bo = bias[o];
        float* dst = outp + (size_t)b * (CIN * 4096) + (size_t)o * 4096 + n0 + tx * 8;
        float4 r0 = make_float4(acc[i][0] + bo, acc[i][1] + bo,
                                acc[i][2] + bo, acc[i][3] + bo);
        float4 r1 = make_float4(acc[i][4] + bo, acc[i][5] + bo,
                                acc[i][6] + bo, acc[i][7] + bo);
        *(float4*)dst = r0;
        *(float4*)(dst + 4) = r1;
    }
}

// ---------------------------------------------------------------------------
extern "C" void kernel_launch(void* const* d_in, const int* in_sizes, int n_in,
                              void* d_out, int out_size)
{
    (void)in_sizes; (void)n_in; (void)out_size;
    const float* x      = (const float*)d_in[0];
    const float* w_qkv  = (const float*)d_in[1];
    const float* b_qkv  = (const float*)d_in[2];
    const float* w_pe   = (const float*)d_in[3];
    const float* b_pe   = (const float*)d_in[4];
    const float* w_proj = (const float*)d_in[5];
    const float* b_proj = (const float*)d_in[6];
    float* out = (float*)d_out;

    cudaFuncSetAttribute(attn_kernel,
                         cudaFuncAttributeMaxDynamicSharedMemorySize,
                         ATT_SMEM_BYTES);

    gemm_qkv_kernel<<<dim3(NGLOB / 128, C3 / 128), 256>>>(x, w_qkv, b_qkv);
    attn_kernel<<<dim3(8, 8, 16), 256, ATT_SMEM_BYTES>>>();
    dwconv_kernel<<<dim3(CIN, 4), 256>>>(w_pe, b_pe);
    gemm_proj_kernel<<<dim3(NGLOB / 128, CIN / 128), 256>>>(w_proj, b_proj, out);
}

// round 2
// speedup vs baseline: 1.8888x; 1.8888x over previous
#include <cuda_runtime.h>
#include <cuda_bf16.h>
#include <math_constants.h>

// ---------------------------------------------------------------------------
//   x:      [4, 256, 64, 64] f32
//   w_qkv:  [768, 256], b_qkv: [768]
//   w_pe:   [256, 1, 7, 7], b_pe: [256]
//   w_proj: [256, 256], b_proj: [256]
//   out:    [4, 256, 64, 64] f32
// Area attention: 16 strips x 8 heads, each 1024x1024x32.
// All matmuls on tensor cores via mma.sync.m16n8k8.tf32 (cvt.rna everywhere).
// ---------------------------------------------------------------------------

#define NGLOB 16384
#define CIN   256
#define C3    768

__device__ float g_qkv[C3 * NGLOB];   // rows: h*96 + {0:q,32:k,64:v} + d
__device__ float g_att[CIN * NGLOB];  // attention out, c = h*32+d
__device__ float g_t  [CIN * NGLOB];  // attn + dwconv(v) + b_pe

__device__ __forceinline__ unsigned f2tf(float x) {
    unsigned r;
    asm("cvt.rna.tf32.f32 %0, %1;" : "=r"(r) : "f"(x));
    return r;
}

__device__ __forceinline__ void mma8(float* c, unsigned a0, unsigned a1,
                                     unsigned a2, unsigned a3,
                                     unsigned b0, unsigned b1) {
    asm volatile(
        "mma.sync.aligned.m16n8k8.row.col.f32.tf32.tf32.f32 "
        "{%0,%1,%2,%3},{%4,%5,%6,%7},{%8,%9},{%0,%1,%2,%3};\n"
        : "+f"(c[0]), "+f"(c[1]), "+f"(c[2]), "+f"(c[3])
        : "r"(a0), "r"(a1), "r"(a2), "r"(a3), "r"(b0), "r"(b1));
}

// ---------------------------------------------------------------------------
// TF32 GEMM: dst[b*db + o*dc + n] = bias[o] + sum_k w[o][k] * src[b*sb + k*sk + n]
// 128x128 tile, ktile 32, 8 warps (2x4), warp tile 64x32.
// ---------------------------------------------------------------------------
__global__ void __launch_bounds__(256) gemm_tf32_kernel(
    const float* __restrict__ w, const float* __restrict__ bias,
    const float* __restrict__ src, int sb, int sk,
    float* __restrict__ dst, int db, int dc)
{
    __shared__ unsigned As[128 * 36];   // [m][k] pitch 36
    __shared__ unsigned Bs[32 * 136];   // [k][n] pitch 136

    const int tid = threadIdx.x;
    const int L = tid & 31;
    const int ww = tid >> 5;
    const int wm = ww >> 2, wn = ww & 3;  // 2 x 4 warp grid
    const int m0g = blockIdx.y * 128;
    const int ng0 = blockIdx.x * 128;
    const int b = ng0 >> 12, n0 = ng0 & 4095;

    float c[4][4][4];
#pragma unroll
    for (int q = 0; q < 4; q++)
#pragma unroll
        for (int f = 0; f < 4; f++)
#pragma unroll
            for (int j = 0; j < 4; j++) c[q][f][j] = 0.f;

    const int lm = tid >> 1, lk = (tid & 1) * 16;      // A loader
    const int bk = tid >> 3, bn0 = (tid & 7) * 16;     // B loader
    const int r = L >> 2, a4 = L & 3;

    for (int kb = 0; kb < CIN; kb += 32) {
        __syncthreads();
        {
            const float* ap = w + (size_t)(m0g + lm) * CIN + kb + lk;
            unsigned* ad = As + lm * 36 + lk;
#pragma unroll
            for (int q = 0; q < 16; q += 4) {
                float4 v = *(const float4*)(ap + q);
                ad[q + 0] = f2tf(v.x); ad[q + 1] = f2tf(v.y);
                ad[q + 2] = f2tf(v.z); ad[q + 3] = f2tf(v.w);
            }
            const float* bp = src + (size_t)b * sb + (size_t)(kb + bk) * sk + n0 + bn0;
            unsigned* bd = Bs + bk * 136 + bn0;
#pragma unroll
            for (int q = 0; q < 16; q += 4) {
                float4 v = *(const float4*)(bp + q);
                bd[q + 0] = f2tf(v.x); bd[q + 1] = f2tf(v.y);
                bd[q + 2] = f2tf(v.z); bd[q + 3] = f2tf(v.w);
            }
        }
        __syncthreads();

#pragma unroll
        for (int t = 0; t < 4; t++) {
            unsigned a[4][4];
#pragma unroll
            for (int q = 0; q < 4; q++) {
                const unsigned* Ab = As + (wm * 64 + 16 * q + r) * 36 + 8 * t + a4;
                a[q][0] = Ab[0];          a[q][1] = Ab[8 * 36];
                a[q][2] = Ab[4];          a[q][3] = Ab[8 * 36 + 4];
            }
#pragma unroll
            for (int f = 0; f < 4; f++) {
                unsigned b0 = Bs[(8 * t + a4) * 136 + wn * 32 + 8 * f + r];
                unsigned b1 = Bs[(8 * t + 4 + a4) * 136 + wn * 32 + 8 * f + r];
#pragma unroll
                for (int q = 0; q < 4; q++)
                    mma8(c[q][f], a[q][0], a[q][1], a[q][2], a[q][3], b0, b1);
            }
        }
    }

#pragma unroll
    for (int q = 0; q < 4; q++) {
        const int o = m0g + wm * 64 + 16 * q + r;
        const float bo0 = bias[o];
        const float bo1 = bias[o + 8];
#pragma unroll
        for (int f = 0; f < 4; f++) {
            const int col = n0 + wn * 32 + 8 * f + 2 * a4;
            float2 v0 = make_float2(c[q][f][0] + bo0, c[q][f][1] + bo0);
            float2 v1 = make_float2(c[q][f][2] + bo1, c[q][f][3] + bo1);
            *(float2*)(dst + (size_t)b * db + (size_t)o * dc + col) = v0;
            *(float2*)(dst + (size_t)b * db + (size_t)(o + 8) * dc + col) = v1;
        }
    }
}

// ---------------------------------------------------------------------------
// Flash attention, tf32 tensor cores.
// grid (8 qtiles, 8 heads, 16 strips), 256 threads (8 warps, m16 each).
// Qs: [i=128][d=32] pitch 36; Ks: [d=32][j=64] pitch 72; Vs: same pitch 76.
// S via mma (m=i,n=j,k=d); P relaid C->A layout via shfl; PV via mma (k=j,n=d).
// ---------------------------------------------------------------------------
__global__ void __launch_bounds__(256, 2) attn_kernel()
{
    __shared__ unsigned Qs[128 * 36];
    __shared__ unsigned Ks[32 * 72];
    __shared__ unsigned Vs[32 * 76];

    const int tid = threadIdx.x;
    const int L = tid & 31;
    const int wrp = tid >> 5;
    const int qt = blockIdx.x, h = blockIdx.y, ba = blockIdx.z;
    const int colbase = (ba >> 2) * 4096 + (ba & 3) * 1024;
    const int qcol = colbase + qt * 128;
    const float scale = 0.17677669529663687f;  // 1/sqrt(32)

    // Load + scale + cvt Q: global [d][i] -> Qs[i][d]
    {
        const int d = tid >> 3;
        const int i0 = (tid & 7) * 16;
        const float* src = g_qkv + (size_t)(h * 96 + d) * NGLOB + qcol + i0;
#pragma unroll
        for (int ii = 0; ii < 16; ii++)
            Qs[(i0 + ii) * 36 + d] = f2tf(src[ii] * scale);
    }

    const int m0 = wrp * 16;
    const int r = L >> 2, a4 = L & 3;

    float ms0 = -CUDART_INF_F, ms1 = -CUDART_INF_F;
    float l0 = 0.f, l1 = 0.f;
    float o[4][4];
#pragma unroll
    for (int g = 0; g < 4; g++)
#pragma unroll
        for (int j = 0; j < 4; j++) o[g][j] = 0.f;

    const int ld_d = tid >> 3, ld_j = (tid & 7) * 8;
    const int src1 = (L & ~3) | (a4 >> 1);
    const int src2 = src1 | 2;
    const bool odd = (a4 & 1);

    for (int jt = 0; jt < 16; jt++) {
        __syncthreads();
        {
            const float* kp = g_qkv + (size_t)(h * 96 + 32 + ld_d) * NGLOB
                              + colbase + jt * 64 + ld_j;
            const float* vp = kp + (size_t)32 * NGLOB;
#pragma unroll
            for (int jj = 0; jj < 8; jj++) {
                Ks[ld_d * 72 + ld_j + jj] = f2tf(kp[jj]);
                Vs[ld_d * 76 + ld_j + jj] = f2tf(vp[jj]);
            }
        }
        __syncthreads();

        // ---- S = Q K^T (m16 x n64, k32) ----
        float c[8][4];
#pragma unroll
        for (int f = 0; f < 8; f++)
#pragma unroll
            for (int j = 0; j < 4; j++) c[f][j] = 0.f;

#pragma unroll
        for (int t = 0; t < 4; t++) {
            const unsigned* qb = Qs + (m0 + r) * 36 + 8 * t + a4;
            unsigned a0 = qb[0], a1 = qb[8 * 36], a2 = qb[4], a3 = qb[8 * 36 + 4];
#pragma unroll
            for (int f = 0; f < 8; f++) {
                unsigned b0 = Ks[(8 * t + a4) * 72 + 8 * f + r];
                unsigned b1 = Ks[(8 * t + 4 + a4) * 72 + 8 * f + r];
                mma8(c[f], a0, a1, a2, a3, b0, b1);
            }
        }

        // ---- online softmax (rows m0+r and m0+r+8) ----
        float mx0 = -CUDART_INF_F, mx1 = -CUDART_INF_F;
#pragma unroll
        for (int f = 0; f < 8; f++) {
            mx0 = fmaxf(mx0, fmaxf(c[f][0], c[f][1]));
            mx1 = fmaxf(mx1, fmaxf(c[f][2], c[f][3]));
        }
        mx0 = fmaxf(mx0, __shfl_xor_sync(0xffffffffu, mx0, 1));
        mx0 = fmaxf(mx0, __shfl_xor_sync(0xffffffffu, mx0, 2));
        mx1 = fmaxf(mx1, __shfl_xor_sync(0xffffffffu, mx1, 1));
        mx1 = fmaxf(mx1, __shfl_xor_sync(0xffffffffu, mx1, 2));

        float mn0 = fmaxf(ms0, mx0), mn1 = fmaxf(ms1, mx1);
        float cf0 = __expf(ms0 - mn0), cf1 = __expf(ms1 - mn1);
        ms0 = mn0; ms1 = mn1;

        float rs0 = 0.f, rs1 = 0.f;
#pragma unroll
        for (int f = 0; f < 8; f++) {
            c[f][0] = __expf(c[f][0] - mn0); rs0 += c[f][0];
            c[f][1] = __expf(c[f][1] - mn0); rs0 += c[f][1];
            c[f][2] = __expf(c[f][2] - mn1); rs1 += c[f][2];
            c[f][3] = __expf(c[f][3] - mn1); rs1 += c[f][3];
        }
        rs0 += __shfl_xor_sync(0xffffffffu, rs0, 1);
        rs0 += __shfl_xor_sync(0xffffffffu, rs0, 2);
        rs1 += __shfl_xor_sync(0xffffffffu, rs1, 1);
        rs1 += __shfl_xor_sync(0xffffffffu, rs1, 2);
        l0 = l0 * cf0 + rs0;
        l1 = l1 * cf1 + rs1;
#pragma unroll
        for (int g = 0; g < 4; g++) {
            o[g][0] *= cf0; o[g][1] *= cf0;
            o[g][2] *= cf1; o[g][3] *= cf1;
        }

        // ---- convert P to tf32 ----
        unsigned p[8][4];
#pragma unroll
        for (int f = 0; f < 8; f++)
#pragma unroll
            for (int j = 0; j < 4; j++) p[f][j] = f2tf(c[f][j]);

        // ---- O += P V (m16 x n32, k64); P C-layout -> A-layout via shfl ----
#pragma unroll
        for (int t = 0; t < 8; t++) {
            unsigned u0 = __shfl_sync(0xffffffffu, p[t][0], src1);
            unsigned u1 = __shfl_sync(0xffffffffu, p[t][1], src1);
            unsigned u2 = __shfl_sync(0xffffffffu, p[t][2], src1);
            unsigned u3 = __shfl_sync(0xffffffffu, p[t][3], src1);
            unsigned w0 = __shfl_sync(0xffffffffu, p[t][0], src2);
            unsigned w1 = __shfl_sync(0xffffffffu, p[t][1], src2);
            unsigned w2 = __shfl_sync(0xffffffffu, p[t][2], src2);
            unsigned w3 = __shfl_sync(0xffffffffu, p[t][3], src2);
            unsigned a0 = odd ? u1 : u0;
            unsigned a1 = odd ? u3 : u2;
            unsigned a2 = odd ? w1 : w0;
            unsigned a3 = odd ? w3 : w2;
#pragma unroll
            for (int g = 0; g < 4; g++) {
                unsigned b0 = Vs[(8 * g + r) * 76 + 8 * t + a4];
                unsigned b1 = Vs[(8 * g + r) * 76 + 8 * t + 4 + a4];
                mma8(o[g], a0, a1, a2, a3, b0, b1);
            }
        }
    }

    // ---- normalize + store to g_att ----
    const float il0 = 1.f / l0, il1 = 1.f / l1;
#pragma unroll
    for (int g = 0; g < 4; g++) {
        const int dd = 8 * g + 2 * a4;
        float* p0 = g_att + (size_t)(h * 32 + dd) * NGLOB + qcol + m0 + r;
        float* p1 = p0 + NGLOB;
        p0[0] = o[g][0] * il0;
        p1[0] = o[g][1] * il0;
        p0[8] = o[g][2] * il1;
        p1[8] = o[g][3] * il1;
    }
}

// ---------------------------------------------------------------------------
// 7x7 depthwise conv on V + attention output + b_pe -> g_t
// ---------------------------------------------------------------------------
__global__ void __launch_bounds__(256) dwconv_kernel(
    const float* __restrict__ wpe, const float* __restrict__ bpe)
{
    __shared__ float sm[70][72];
    __shared__ float wk[49];

    const int c = blockIdx.x, b = blockIdx.y;
    const int tid = threadIdx.x;

    for (int i = tid; i < 70 * 72; i += 256) (&sm[0][0])[i] = 0.f;
    if (tid < 49) wk[tid] = wpe[c * 49 + tid];
    __syncthreads();

    const int vrow = (c >> 5) * 96 + 64 + (c & 31);
    const float* vsrc = g_qkv + (size_t)vrow * NGLOB + b * 4096;
    const int r  = tid >> 2;
    const int c0 = (tid & 3) * 16;
#pragma unroll
    for (int q = 0; q < 16; q += 4) {
        float4 v = *(const float4*)(vsrc + r * 64 + c0 + q);
        sm[3 + r][3 + c0 + q + 0] = v.x;
        sm[3 + r][3 + c0 + q + 1] = v.y;
        sm[3 + r][3 + c0 + q + 2] = v.z;
        sm[3 + r][3 + c0 + q + 3] = v.w;
    }
    __syncthreads();

    const float* asrc = g_att + (size_t)c * NGLOB + b * 4096;
    const float bb = bpe[c];
    float out[16];
#pragma unroll
    for (int q = 0; q < 16; q += 4) {
        float4 a = *(const float4*)(asrc + r * 64 + c0 + q);
        out[q + 0] = a.x + bb; out[q + 1] = a.y + bb;
        out[q + 2] = a.z + bb; out[q + 3] = a.w + bb;
    }

#pragma unroll
    for (int ky = 0; ky < 7; ky++) {
        float row[22];
#pragma unroll
        for (int q = 0; q < 22; q++) row[q] = sm[r + ky][c0 + q];
#pragma unroll
        for (int kx = 0; kx < 7; kx++) {
            const float wv = wk[ky * 7 + kx];
#pragma unroll
            for (int xx = 0; xx < 16; xx++) out[xx] += wv * row[xx + kx];
        }
    }

    float* dst = g_t + (size_t)c * NGLOB + b * 4096 + r * 64 + c0;
#pragma unroll
    for (int q = 0; q < 16; q += 4)
        *(float4*)(dst + q) = make_float4(out[q], out[q + 1], out[q + 2], out[q + 3]);
}

// ---------------------------------------------------------------------------
extern "C" void kernel_launch(void* const* d_in, const int* in_sizes, int n_in,
                              void* d_out, int out_size)
{
    (void)in_sizes; (void)n_in; (void)out_size;
    const float* x      = (const float*)d_in[0];
    const float* w_qkv  = (const float*)d_in[1];
    const float* b_qkv  = (const float*)d_in[2];
    const float* w_pe   = (const float*)d_in[3];
    const float* b_pe   = (const float*)d_in[4];
    const float* w_proj = (const float*)d_in[5];
    const float* b_proj = (const float*)d_in[6];
    float* out = (float*)d_out;

    float* g_qkv_p; cudaGetSymbolAddress((void**)&g_qkv_p, g_qkv);
    float* g_t_p;   cudaGetSymbolAddress((void**)&g_t_p, g_t);

    // qkv: dst g_qkv (chan-major), src x (batch-major NCHW)
    gemm_tf32_kernel<<<dim3(NGLOB / 128, C3 / 128), 256>>>(
        w_qkv, b_qkv, x, 256 * 4096, 4096, g_qkv_p, 4096, NGLOB);

    attn_kernel<<<dim3(8, 8, 16), 256>>>();

    dwconv_kernel<<<dim3(CIN, 4), 256>>>(w_pe, b_pe);

    // proj: dst out (NCHW), src g_t (chan-major)
    gemm_tf32_kernel<<<dim3(NGLOB / 128, CIN / 128), 256>>>(
        w_proj, b_proj, g_t_p, 4096, NGLOB, out, 256 * 4096, 4096);
}

// round 3
// speedup vs baseline: 2.4022x; 1.2718x over previous
#include <cuda_runtime.h>
#include <cuda_bf16.h>
#include <math_constants.h>

// ---------------------------------------------------------------------------
//   x: [4,256,64,64] f32; w_qkv:[768,256]; w_pe:[256,1,7,7]; w_proj:[256,256]
//   out: [4,256,64,64] f32.  Area attention: 16 strips x 8 heads, 1024x1024x32.
//   All matmuls: mma.sync.m16n8k8.tf32 (cvt.rna), fragment-major smem staging,
//   double-buffered pipelines, Q resident in registers.
// ---------------------------------------------------------------------------

#define NGLOB 16384
#define CIN   256
#define C3    768

__device__ float g_qkv[C3 * NGLOB];   // rows: h*96 + {0:q,32:k,64:v} + d
__device__ float g_att[CIN * NGLOB];
__device__ float g_t  [CIN * NGLOB];

__device__ __forceinline__ unsigned f2tf(float x) {
    unsigned r;
    asm("cvt.rna.tf32.f32 %0, %1;" : "=r"(r) : "f"(x));
    return r;
}

__device__ __forceinline__ void mma8(float* c, unsigned a0, unsigned a1,
                                     unsigned a2, unsigned a3,
                                     unsigned b0, unsigned b1) {
    asm volatile(
        "mma.sync.aligned.m16n8k8.row.col.f32.tf32.tf32.f32 "
        "{%0,%1,%2,%3},{%4,%5,%6,%7},{%8,%9},{%0,%1,%2,%3};\n"
        : "+f"(c[0]), "+f"(c[1]), "+f"(c[2]), "+f"(c[3])
        : "r"(a0), "r"(a1), "r"(a2), "r"(a3), "r"(b0), "r"(b1));
}

// ---------------------------------------------------------------------------
// TF32 GEMM, fragment-major double-buffered.
// dst[b*db + o*dc + n] = bias[o] + sum_k w[o][k]*src[b*sb + k*sk + n]
// CTA 128x128, ktile 32, 8 warps (2x4), warp tile 64x32.
// A frags: 64 groups (q'[8] x t[4] x u[2]) of 66 words; lane pair {row r, row r+8}.
// B frags: 64 groups ((t*4+f)*4+wn) of 66 words; lane pair {k, k+4}.
// ---------------------------------------------------------------------------
#define GA_WORDS (64 * 66)      // 4224
#define GBUF     (2 * GA_WORDS) // 8448 words per buffer (A then B)
#define GSMEM_BYTES (2 * GBUF * 4)

__global__ void __launch_bounds__(256) gemm_tf32_kernel(
    const float* __restrict__ w, const float* __restrict__ bias,
    const float* __restrict__ src, int sb, int sk,
    float* __restrict__ dst, int db, int dc)
{
    extern __shared__ unsigned dynsm[];
    const int tid = threadIdx.x;
    const int L = tid & 31;
    const int ww = tid >> 5;
    const int wm = ww >> 2, wn = ww & 3;
    const int m0g = blockIdx.y * 128;
    const int ng0 = blockIdx.x * 128;
    const int b = ng0 >> 12, n0 = ng0 & 4095;

    // A loader: 16 consecutive k per thread
    const int lm = tid >> 1, lk = (tid & 1) * 16;
    const int aq = lm >> 4, arr = lm & 7, ass = (lm >> 3) & 1;
    // B loader: 16 consecutive n per thread
    const int bk = tid >> 3, bn0 = (tid & 7) * 16;
    const int bt = bk >> 3, ba4 = bk & 3, bu = (bk >> 2) & 1;

    float c[4][4][4];
#pragma unroll
    for (int q = 0; q < 4; q++)
#pragma unroll
        for (int f = 0; f < 4; f++)
#pragma unroll
            for (int j = 0; j < 4; j++) c[q][f][j] = 0.f;

    float4 areg[4], breg[4];

    auto ldAB = [&](int kb) {
        const float* ap = w + (size_t)(m0g + lm) * CIN + kb + lk;
        areg[0] = *(const float4*)ap;
        areg[1] = *(const float4*)(ap + 4);
        areg[2] = *(const float4*)(ap + 8);
        areg[3] = *(const float4*)(ap + 12);
        const float* bp = src + (size_t)b * sb + (size_t)(kb + bk) * sk + n0 + bn0;
        breg[0] = *(const float4*)bp;
        breg[1] = *(const float4*)(bp + 4);
        breg[2] = *(const float4*)(bp + 8);
        breg[3] = *(const float4*)(bp + 12);
    };

    auto stAB = [&](unsigned* buf) {
        unsigned* As = buf;
        unsigned* Bs = buf + GA_WORDS;
#pragma unroll
        for (int j = 0; j < 4; j++) {
            float va[4] = {areg[j].x, areg[j].y, areg[j].z, areg[j].w};
            float vb[4] = {breg[j].x, breg[j].y, breg[j].z, breg[j].w};
#pragma unroll
            for (int l = 0; l < 4; l++) {
                const int kk = lk + j * 4 + l;
                const int t = kk >> 3, a4 = kk & 3, u = (kk >> 2) & 1;
                As[(aq * 8 + t * 2 + u) * 66 + (arr * 4 + a4) * 2 + ass] = f2tf(va[l]);
                const int n = bn0 + j * 4 + l;
                const int wnn = n >> 5, f = (n >> 3) & 3, r = n & 7;
                Bs[((bt * 4 + f) * 4 + wnn) * 66 + (r * 4 + ba4) * 2 + bu] = f2tf(vb[l]);
            }
        }
    };

    auto comp = [&](const unsigned* buf) {
        const unsigned* As = buf;
        const unsigned* Bs = buf + GA_WORDS;
#pragma unroll
        for (int t = 0; t < 4; t++) {
            uint2 aLo[4], aHi[4];
#pragma unroll
            for (int q = 0; q < 4; q++) {
                const unsigned* p0 = As + ((wm * 4 + q) * 8 + t * 2) * 66 + L * 2;
                aLo[q] = *(const uint2*)p0;
                aHi[q] = *(const uint2*)(p0 + 66);
            }
#pragma unroll
            for (int f = 0; f < 4; f++) {
                uint2 bb = *(const uint2*)(Bs + ((t * 4 + f) * 4 + wn) * 66 + L * 2);
#pragma unroll
                for (int q = 0; q < 4; q++)
                    mma8(c[q][f], aLo[q].x, aLo[q].y, aHi[q].x, aHi[q].y, bb.x, bb.y);
            }
        }
    };

    ldAB(0);
    stAB(dynsm);
    __syncthreads();
#pragma unroll 1
    for (int kt = 0; kt < 8; kt++) {
        if (kt < 7) ldAB((kt + 1) * 32);
        comp(dynsm + (kt & 1) * GBUF);
        if (kt < 7) stAB(dynsm + ((kt + 1) & 1) * GBUF);
        __syncthreads();
    }

    const int r = L >> 2, a4 = L & 3;
#pragma unroll
    for (int q = 0; q < 4; q++) {
        const int o = m0g + wm * 64 + 16 * q + r;
        const float bo0 = bias[o];
        const float bo1 = bias[o + 8];
#pragma unroll
        for (int f = 0; f < 4; f++) {
            const int col = n0 + wn * 32 + 8 * f + 2 * a4;
            float2 v0 = make_float2(c[q][f][0] + bo0, c[q][f][1] + bo0);
            float2 v1 = make_float2(c[q][f][2] + bo1, c[q][f][3] + bo1);
            *(float2*)(dst + (size_t)b * db + (size_t)o * dc + col) = v0;
            *(float2*)(dst + (size_t)b * db + (size_t)(o + 8) * dc + col) = v1;
        }
    }
}

// ---------------------------------------------------------------------------
// Flash attention: 8 warps x m16, BJ=64, double-buffered K/V, Q in registers.
// K frags: 32 groups (f*4+t) x 68 words; lane pair {d, d+4}.
// V frags: 32 groups (t*4+g) x 68 words; lane pair {j, j+4}.
// Q staged transiently in buf1 region, fragment-major (GEMM-A style).
// ---------------------------------------------------------------------------
#define KV_WORDS (32 * 68)       // 2176
#define ABUF     (2 * KV_WORDS)  // 4352 per buffer (K then V)

__global__ void __launch_bounds__(256, 2) attn_kernel()
{
    __shared__ unsigned sm[2 * ABUF];   // 34816 B

    const int tid = threadIdx.x;
    const int L = tid & 31;
    const int wrp = tid >> 5;
    const int r = L >> 2, a4 = L & 3;
    const int qt = blockIdx.x, h = blockIdx.y, ba = blockIdx.z;
    const int colbase = (ba >> 2) * 4096 + (ba & 3) * 1024;
    const int qcol = colbase + qt * 128;
    const float scale = 0.17677669529663687f;  // 1/sqrt(32)

    // ---- stage Q (fragment-major) into buf1 region ----
    {
        const int d = tid >> 3;
        const int i0 = (tid & 7) * 16;
        const int t = d >> 3, qa4 = d & 3, u = (d >> 2) & 1;
        const float* srcq = g_qkv + (size_t)(h * 96 + d) * NGLOB + qcol + i0;
        unsigned* Qs = sm + ABUF;
#pragma unroll
        for (int ii = 0; ii < 16; ii++) {
            const int i = i0 + ii;
            const int qp = i >> 4, s = (i >> 3) & 1, rr = i & 7;
            Qs[(qp * 8 + t * 2 + u) * 66 + (rr * 4 + qa4) * 2 + s] = f2tf(srcq[ii] * scale);
        }
    }

    // loader geometry for K/V
    const int ld_d = tid >> 3, ld_j = (tid & 7) * 8;
    const int kt_ = ld_d >> 3, ka4 = ld_d & 3, ku = (ld_d >> 2) & 1;  // from d
    const int kf = tid & 7;                                            // j block
    const int vg = ld_d >> 3, vr = ld_d & 7;                           // dd comps
    const int vt = tid & 7;                                            // j block
    const float* kbase = g_qkv + (size_t)(h * 96 + 32 + ld_d) * NGLOB + colbase + ld_j;
    const float* vbase = kbase + (size_t)32 * NGLOB;

    auto stKV = [&](unsigned* buf, float4 k0, float4 k1, float4 v0, float4 v1) {
        unsigned* K = buf;
        unsigned* V = buf + KV_WORDS;
        float kv[8] = {k0.x, k0.y, k0.z, k0.w, k1.x, k1.y, k1.z, k1.w};
#pragma unroll
        for (int jj = 0; jj < 8; jj++)
            K[(kf * 4 + kt_) * 68 + jj * 8 + ka4 * 2 + ku] = f2tf(kv[jj]);
        float vv[8] = {v0.x, v0.y, v0.z, v0.w, v1.x, v1.y, v1.z, v1.w};
        uint4 p0 = make_uint4(f2tf(vv[0]), f2tf(vv[4]), f2tf(vv[1]), f2tf(vv[5]));
        uint4 p1 = make_uint4(f2tf(vv[2]), f2tf(vv[6]), f2tf(vv[3]), f2tf(vv[7]));
        unsigned* vd = V + (vt * 4 + vg) * 68 + vr * 8;
        *(uint4*)vd = p0;
        *(uint4*)(vd + 4) = p1;
    };

    // stage K/V jt=0 into buf0
    {
        float4 k0 = *(const float4*)kbase;
        float4 k1 = *(const float4*)(kbase + 4);
        float4 v0 = *(const float4*)vbase;
        float4 v1 = *(const float4*)(vbase + 4);
        stKV(sm, k0, k1, v0, v1);
    }
    __syncthreads();

    // ---- Q fragments to registers ----
    unsigned qf[4][4];
    {
        const unsigned* Qs = sm + ABUF;
#pragma unroll
        for (int t = 0; t < 4; t++) {
            uint2 lo = *(const uint2*)(Qs + (wrp * 8 + t * 2) * 66 + L * 2);
            uint2 hi = *(const uint2*)(Qs + (wrp * 8 + t * 2 + 1) * 66 + L * 2);
            qf[t][0] = lo.x; qf[t][1] = lo.y; qf[t][2] = hi.x; qf[t][3] = hi.y;
        }
    }
    __syncthreads();

    float ms0 = -CUDART_INF_F, ms1 = -CUDART_INF_F;
    float l0 = 0.f, l1 = 0.f;
    float o[4][4];
#pragma unroll
    for (int g = 0; g < 4; g++)
#pragma unroll
        for (int j = 0; j < 4; j++) o[g][j] = 0.f;

    const int src1 = (L & ~3) | (a4 >> 1);
    const int src2 = src1 | 2;
    const bool odd = (a4 & 1);

#pragma unroll 1
    for (int jt = 0; jt < 16; jt++) {
        float4 k0, k1, v0, v1;
        if (jt < 15) {
            const float* kp = kbase + (jt + 1) * 64;
            const float* vp = vbase + (jt + 1) * 64;
            k0 = *(const float4*)kp;
            k1 = *(const float4*)(kp + 4);
            v0 = *(const float4*)vp;
            v1 = *(const float4*)(vp + 4);
        }
        const unsigned* K = sm + (jt & 1) * ABUF;
        const unsigned* V = K + KV_WORDS;

        // ---- S = Q K^T ----
        float c[8][4];
#pragma unroll
        for (int f = 0; f < 8; f++)
#pragma unroll
            for (int j = 0; j < 4; j++) c[f][j] = 0.f;

#pragma unroll
        for (int t = 0; t < 4; t++) {
#pragma unroll
            for (int f = 0; f < 8; f++) {
                uint2 kb2 = *(const uint2*)(K + (f * 4 + t) * 68 + L * 2);
                mma8(c[f], qf[t][0], qf[t][1], qf[t][2], qf[t][3], kb2.x, kb2.y);
            }
        }

        // ---- online softmax ----
        float mx0 = -CUDART_INF_F, mx1 = -CUDART_INF_F;
#pragma unroll
        for (int f = 0; f < 8; f++) {
            mx0 = fmaxf(mx0, fmaxf(c[f][0], c[f][1]));
            mx1 = fmaxf(mx1, fmaxf(c[f][2], c[f][3]));
        }
        mx0 = fmaxf(mx0, __shfl_xor_sync(0xffffffffu, mx0, 1));
        mx0 = fmaxf(mx0, __shfl_xor_sync(0xffffffffu, mx0, 2));
        mx1 = fmaxf(mx1, __shfl_xor_sync(0xffffffffu, mx1, 1));
        mx1 = fmaxf(mx1, __shfl_xor_sync(0xffffffffu, mx1, 2));

        float mn0 = fmaxf(ms0, mx0), mn1 = fmaxf(ms1, mx1);
        float cf0 = __expf(ms0 - mn0), cf1 = __expf(ms1 - mn1);
        ms0 = mn0; ms1 = mn1;

        float rs0 = 0.f, rs1 = 0.f;
#pragma unroll
        for (int f = 0; f < 8; f++) {
            c[f][0] = __expf(c[f][0] - mn0); rs0 += c[f][0];
            c[f][1] = __expf(c[f][1] - mn0); rs0 += c[f][1];
            c[f][2] = __expf(c[f][2] - mn1); rs1 += c[f][2];
            c[f][3] = __expf(c[f][3] - mn1); rs1 += c[f][3];
        }
        rs0 += __shfl_xor_sync(0xffffffffu, rs0, 1);
        rs0 += __shfl_xor_sync(0xffffffffu, rs0, 2);
        rs1 += __shfl_xor_sync(0xffffffffu, rs1, 1);
        rs1 += __shfl_xor_sync(0xffffffffu, rs1, 2);
        l0 = l0 * cf0 + rs0;
        l1 = l1 * cf1 + rs1;
#pragma unroll
        for (int g = 0; g < 4; g++) {
            o[g][0] *= cf0; o[g][1] *= cf0;
            o[g][2] *= cf1; o[g][3] *= cf1;
        }

        // ---- O += P V (lazy tf32 cvt; C->A layout via shfl) ----
#pragma unroll
        for (int t = 0; t < 8; t++) {
            unsigned p0 = f2tf(c[t][0]);
            unsigned p1 = f2tf(c[t][1]);
            unsigned p2 = f2tf(c[t][2]);
            unsigned p3 = f2tf(c[t][3]);
            unsigned u0 = __shfl_sync(0xffffffffu, p0, src1);
            unsigned u1 = __shfl_sync(0xffffffffu, p1, src1);
            unsigned u2 = __shfl_sync(0xffffffffu, p2, src1);
            unsigned u3 = __shfl_sync(0xffffffffu, p3, src1);
            unsigned w0 = __shfl_sync(0xffffffffu, p0, src2);
            unsigned w1 = __shfl_sync(0xffffffffu, p1, src2);
            unsigned w2 = __shfl_sync(0xffffffffu, p2, src2);
            unsigned w3 = __shfl_sync(0xffffffffu, p3, src2);
            unsigned a0 = odd ? u1 : u0;
            unsigned a1 = odd ? u3 : u2;
            unsigned a2 = odd ? w1 : w0;
            unsigned a3 = odd ? w3 : w2;
#pragma unroll
            for (int g = 0; g < 4; g++) {
                uint2 vb = *(const uint2*)(V + (t * 4 + g) * 68 + L * 2);
                mma8(o[g], a0, a1, a2, a3, vb.x, vb.y);
            }
        }

        if (jt < 15)
            stKV(sm + ((jt + 1) & 1) * ABUF, k0, k1, v0, v1);
        __syncthreads();
    }

    // ---- normalize + store ----
    const float il0 = 1.f / l0, il1 = 1.f / l1;
    const int m0 = wrp * 16;
#pragma unroll
    for (int g = 0; g < 4; g++) {
        const int dd = 8 * g + 2 * a4;
        float* p0 = g_att + (size_t)(h * 32 + dd) * NGLOB + qcol + m0 + r;
        float* p1 = p0 + NGLOB;
        p0[0] = o[g][0] * il0;
        p1[0] = o[g][1] * il0;
        p0[8] = o[g][2] * il1;
        p1[8] = o[g][3] * il1;
    }
}

// ---------------------------------------------------------------------------
// 7x7 depthwise conv on V + attention output + b_pe -> g_t
// ---------------------------------------------------------------------------
__global__ void __launch_bounds__(256) dwconv_kernel(
    const float* __restrict__ wpe, const float* __restrict__ bpe)
{
    __shared__ float smv[70][72];
    __shared__ float wk[49];

    const int c = blockIdx.x, b = blockIdx.y;
    const int tid = threadIdx.x;

    for (int i = tid; i < 70 * 72; i += 256) (&smv[0][0])[i] = 0.f;
    if (tid < 49) wk[tid] = wpe[c * 49 + tid];
    __syncthreads();

    const int vrow = (c >> 5) * 96 + 64 + (c & 31);
    const float* vsrc = g_qkv + (size_t)vrow * NGLOB + b * 4096;
    const int r  = tid >> 2;
    const int c0 = (tid & 3) * 16;
#pragma unroll
    for (int q = 0; q < 16; q += 4) {
        float4 v = *(const float4*)(vsrc + r * 64 + c0 + q);
        smv[3 + r][3 + c0 + q + 0] = v.x;
        smv[3 + r][3 + c0 + q + 1] = v.y;
        smv[3 + r][3 + c0 + q + 2] = v.z;
        smv[3 + r][3 + c0 + q + 3] = v.w;
    }
    __syncthreads();

    const float* asrc = g_att + (size_t)c * NGLOB + b * 4096;
    const float bb = bpe[c];
    float out[16];
#pragma unroll
    for (int q = 0; q < 16; q += 4) {
        float4 a = *(const float4*)(asrc + r * 64 + c0 + q);
        out[q + 0] = a.x + bb; out[q + 1] = a.y + bb;
        out[q + 2] = a.z + bb; out[q + 3] = a.w + bb;
    }

#pragma unroll
    for (int ky = 0; ky < 7; ky++) {
        float row[22];
#pragma unroll
        for (int q = 0; q < 22; q++) row[q] = smv[r + ky][c0 + q];
#pragma unroll
        for (int kx = 0; kx < 7; kx++) {
            const float wv = wk[ky * 7 + kx];
#pragma unroll
            for (int xx = 0; xx < 16; xx++) out[xx] += wv * row[xx + kx];
        }
    }

    float* dst = g_t + (size_t)c * NGLOB + b * 4096 + r * 64 + c0;
#pragma unroll
    for (int q = 0; q < 16; q += 4)
        *(float4*)(dst + q) = make_float4(out[q], out[q + 1], out[q + 2], out[q + 3]);
}

// ---------------------------------------------------------------------------
extern "C" void kernel_launch(void* const* d_in, const int* in_sizes, int n_in,
                              void* d_out, int out_size)
{
    (void)in_sizes; (void)n_in; (void)out_size;
    const float* x      = (const float*)d_in[0];
    const float* w_qkv  = (const float*)d_in[1];
    const float* b_qkv  = (const float*)d_in[2];
    const float* w_pe   = (const float*)d_in[3];
    const float* b_pe   = (const float*)d_in[4];
    const float* w_proj = (const float*)d_in[5];
    const float* b_proj = (const float*)d_in[6];
    float* out = (float*)d_out;

    float* g_qkv_p; cudaGetSymbolAddress((void**)&g_qkv_p, g_qkv);
    float* g_t_p;   cudaGetSymbolAddress((void**)&g_t_p, g_t);

    cudaFuncSetAttribute(gemm_tf32_kernel,
                         cudaFuncAttributeMaxDynamicSharedMemorySize, GSMEM_BYTES);

    gemm_tf32_kernel<<<dim3(NGLOB / 128, C3 / 128), 256, GSMEM_BYTES>>>(
        w_qkv, b_qkv, x, 256 * 4096, 4096, g_qkv_p, 4096, NGLOB);

    attn_kernel<<<dim3(8, 8, 16), 256>>>();

    dwconv_kernel<<<dim3(CIN, 4), 256>>>(w_pe, b_pe);

    gemm_tf32_kernel<<<dim3(NGLOB / 128, CIN / 128), 256, GSMEM_BYTES>>>(
        w_proj, b_proj, g_t_p, 4096, NGLOB, out, 256 * 4096, 4096);
}